// round 9
// baseline (speedup 1.0000x reference)
#include <cuda_runtime.h>
#include <cuda_bf16.h>

// 3-layer LSTM, B=1024, T=1024, H=20, IN=1, OUT=2, FC on last h2.
// R9: layer-specialized pipeline, 4 pipelines x 3 warps per block (GB=2
// batches each), grid 128 (1 block/SM -> 12 warps/SM, 3 per SMSP).
// L1/L2 weights hybrid: input-half register-resident, recurrent-half in SMEM
// (k-pair packed, pad-6 conflict-free). Sync = named barrier per pipeline
// (bar.sync 1+pipe, 96) so pipelines are decoupled.

#define T_LEN 1024
#define HID   20
#define GB    2           // batches per pipeline
#define NPIPE 4
#define NW    (3 * NPIPE) // 12 warps
#define FULLM 0xffffffffu

typedef unsigned long long u64;

__device__ __forceinline__ void ffma2(u64 &acc, u64 a, u64 b) {
    asm("fma.rn.f32x2 %0, %1, %2, %0;" : "+l"(acc) : "l"(a), "l"(b));
}
__device__ __forceinline__ u64 pack2f(float lo, float hi) {
    u64 r; asm("mov.b64 %0, {%1, %2};" : "=l"(r) : "f"(lo), "f"(hi)); return r;
}
__device__ __forceinline__ void unpack2(float &lo, float &hi, u64 v) {
    asm("mov.b64 {%0, %1}, %2;" : "=f"(lo), "=f"(hi) : "l"(v));
}

// ---- accurate fast activations (MUFU EX2/RCP, ~1e-6 err) ----
__device__ __forceinline__ float fsig(float x) {
    float e = __expf(-x);
    return __fdividef(1.0f, 1.0f + e);
}
__device__ __forceinline__ float ftanh(float x) {
    float ax = fabsf(x);
    float e  = __expf(-2.0f * ax);
    float r  = __fdividef(1.0f - e, 1.0f + e);
    return copysignf(r, x);
}
__device__ __forceinline__ float cellup(float pi, float pf, float pg, float po,
                                        float &c) {
    c = fsig(pf) * c + fsig(pi) * ftanh(pg);
    return fsig(po) * ftanh(c);
}

// 20 k-steps against register weights W[g*10+m] (40 u64)
__device__ __forceinline__ void mac5_reg(u64 &a0, u64 &a1, u64 &a2, u64 &a3,
                                         const float4* __restrict__ hbuf,
                                         const u64* __restrict__ W)
{
    const ulonglong2* q = (const ulonglong2*)hbuf;
#pragma unroll
    for (int i = 0; i < 5; i++) {
        ulonglong2 v = q[i];              // {h4i,h4i+1},{h4i+2,h4i+3}
        ffma2(a0, v.x, W[2*i]);      ffma2(a1, v.x, W[10 + 2*i]);
        ffma2(a2, v.x, W[20 + 2*i]); ffma2(a3, v.x, W[30 + 2*i]);
        ffma2(a0, v.y, W[2*i + 1]);      ffma2(a1, v.y, W[10 + 2*i + 1]);
        ffma2(a2, v.y, W[20 + 2*i + 1]); ffma2(a3, v.y, W[30 + 2*i + 1]);
    }
}

// 20 k-steps against SMEM weights. wsm = &s_wr[lay][0][j][0];
// layout [10 kpair][20 j][6 pad] u64: per kpair m, lane j reads
// {Wi,Wf} and {Wg,Wo} as two LDS.128 (conflict-free at 48B j-stride).
#define WR_MSTRIDE (20 * 6)
__device__ __forceinline__ void mac5_sm(u64 &a0, u64 &a1, u64 &a2, u64 &a3,
                                        const float4* __restrict__ hbuf,
                                        const u64* __restrict__ wsm)
{
    const ulonglong2* q = (const ulonglong2*)hbuf;
#pragma unroll
    for (int i = 0; i < 5; i++) {
        ulonglong2 v = q[i];
        const u64* w0 = wsm + (2 * i) * WR_MSTRIDE;
        const u64* w1 = wsm + (2 * i + 1) * WR_MSTRIDE;
        ulonglong2 wa = *(const ulonglong2*)(w0);      // {Wi,Wf} kpair 2i
        ulonglong2 wb = *(const ulonglong2*)(w0 + 2);  // {Wg,Wo}
        ffma2(a0, v.x, wa.x); ffma2(a1, v.x, wa.y);
        ffma2(a2, v.x, wb.x); ffma2(a3, v.x, wb.y);
        ulonglong2 wc = *(const ulonglong2*)(w1);
        ulonglong2 wd = *(const ulonglong2*)(w1 + 2);
        ffma2(a0, v.y, wc.x); ffma2(a1, v.y, wc.y);
        ffma2(a2, v.y, wd.x); ffma2(a3, v.y, wd.y);
    }
}

__global__ void __launch_bounds__(NW * 32, 1)
lstm3_pipe(const float* __restrict__ x,
           const float* __restrict__ wih0, const float* __restrict__ whh0,
           const float* __restrict__ bih0, const float* __restrict__ bhh0,
           const float* __restrict__ wih1, const float* __restrict__ whh1,
           const float* __restrict__ bih1, const float* __restrict__ bhh1,
           const float* __restrict__ wih2, const float* __restrict__ whh2,
           const float* __restrict__ bih2, const float* __restrict__ bhh2,
           const float* __restrict__ fcw,  const float* __restrict__ fcb,
           float* __restrict__ out)
{
    // recurrent-half weights for L1 (lay 0) and L2 (lay 1)
    __shared__ u64 s_wr[2][10][HID][6];
    // h buffers: [layer][pipe][parity][batch][5 x float4 = 20 floats]
    __shared__ float4 s_h[3][NPIPE][2][GB][5];

    const int tid  = threadIdx.x;
    const int lane = tid & 31;
    const int wid  = tid >> 5;

    // ---- stage recurrent halves of whh1/whh2 (k-pair packed) ----
    for (int idx = tid; idx < 2 * 10 * HID; idx += NW * 32) {
        int lay = idx / (10 * HID);
        int r   = idx % (10 * HID);
        int m   = r / HID;
        int j   = r % HID;
        const float* wh = lay ? whh2 : whh1;
#pragma unroll
        for (int g = 0; g < 4; g++)
            s_wr[lay][m][j][g] = *(const u64*)(wh + (g * HID + j) * HID + 2 * m);
    }
    // zero h buffers
    {
        float4* p = &s_h[0][0][0][0][0];
        for (int i = tid; i < 3 * NPIPE * 2 * GB * 5; i += NW * 32)
            p[i] = make_float4(0.f, 0.f, 0.f, 0.f);
    }
    __syncthreads();

    // role map: pipe = wid/3, role = wid%3 -> each SMSP gets one of each role
    const int pipe = wid / 3;
    const int role = wid % 3;             // 0=L0, 1=L1, 2=L2
    const int bar_id = 1 + pipe;

    const int j     = (lane < HID) ? lane : (HID - 1);
    const int bbase = blockIdx.x * (NPIPE * GB) + pipe * GB;

    // ---- register-resident weights ----
    u64   W[40];            // L0: whh0 | L1: wih1 | L2: wih2 (k-pair per gate)
    float wx4[4];
    u64   Binit[4];
    {
        const float* wreg = (role == 0) ? whh0 : ((role == 1) ? wih1 : wih2);
        const float* bi   = (role == 0) ? bih0 : ((role == 1) ? bih1 : bih2);
        const float* bh   = (role == 0) ? bhh0 : ((role == 1) ? bhh1 : bhh2);
#pragma unroll
        for (int g = 0; g < 4; g++) {
            const float* wr = wreg + (g * HID + j) * HID;
#pragma unroll
            for (int m = 0; m < 10; m++) W[g * 10 + m] = *(const u64*)(wr + 2 * m);
            Binit[g] = pack2f(bi[g * HID + j] + bh[g * HID + j], 0.f);
            if (role == 0) wx4[g] = wih0[g * HID + j];
        }
    }
    const u64* wsm = (role >= 1) ? &s_wr[role - 1][0][j][0] : (const u64*)0;

    float cst[GB] = {0.f, 0.f};
    float xs[GB];

    // pipeline: step n -> L0 computes t=n, L1 t=n-1, L2 t=n-2
    for (int n = 0; n <= T_LEN + 1; n++) {
        if (role == 0) {
            if (n < T_LEN) {
                if ((n & 31) == 0) {
#pragma unroll
                    for (int gb = 0; gb < GB; gb++)
                        xs[gb] = x[(bbase + gb) * T_LEN + n + lane];
                }
                const int pw = n & 1, pr = pw ^ 1;
#pragma unroll
                for (int gb = 0; gb < GB; gb++) {
                    float xv = __shfl_sync(FULLM, xs[gb], n & 31);
                    u64 a0 = Binit[0], a1 = Binit[1], a2 = Binit[2], a3 = Binit[3];
                    mac5_reg(a0, a1, a2, a3, s_h[0][pipe][pr][gb], W);
                    float lo, hi, pi, pf, pg, po;
                    unpack2(lo, hi, a0); pi = lo + hi + xv * wx4[0];
                    unpack2(lo, hi, a1); pf = lo + hi + xv * wx4[1];
                    unpack2(lo, hi, a2); pg = lo + hi + xv * wx4[2];
                    unpack2(lo, hi, a3); po = lo + hi + xv * wx4[3];
                    float hn = cellup(pi, pf, pg, po, cst[gb]);
                    if (lane < HID) ((float*)s_h[0][pipe][pw][gb])[lane] = hn;
                }
            }
        } else if (role == 1) {
            if (n >= 1 && n <= T_LEN) {
                const int t = n - 1, pw = t & 1, pr = pw ^ 1;
#pragma unroll
                for (int gb = 0; gb < GB; gb++) {
                    u64 a0 = Binit[0], a1 = Binit[1], a2 = Binit[2], a3 = Binit[3];
                    mac5_reg(a0, a1, a2, a3, s_h[0][pipe][pw][gb], W);    // h0[t]
                    mac5_sm (a0, a1, a2, a3, s_h[1][pipe][pr][gb], wsm);  // h1[t-1]
                    float lo, hi, pi, pf, pg, po;
                    unpack2(lo, hi, a0); pi = lo + hi;
                    unpack2(lo, hi, a1); pf = lo + hi;
                    unpack2(lo, hi, a2); pg = lo + hi;
                    unpack2(lo, hi, a3); po = lo + hi;
                    float hn = cellup(pi, pf, pg, po, cst[gb]);
                    if (lane < HID) ((float*)s_h[1][pipe][pw][gb])[lane] = hn;
                }
            }
        } else {
            if (n >= 2) {
                const int t = n - 2, pw = t & 1, pr = pw ^ 1;
#pragma unroll
                for (int gb = 0; gb < GB; gb++) {
                    u64 a0 = Binit[0], a1 = Binit[1], a2 = Binit[2], a3 = Binit[3];
                    mac5_reg(a0, a1, a2, a3, s_h[1][pipe][pw][gb], W);    // h1[t]
                    mac5_sm (a0, a1, a2, a3, s_h[2][pipe][pr][gb], wsm);  // h2[t-1]
                    float lo, hi, pi, pf, pg, po;
                    unpack2(lo, hi, a0); pi = lo + hi;
                    unpack2(lo, hi, a1); pf = lo + hi;
                    unpack2(lo, hi, a2); pg = lo + hi;
                    unpack2(lo, hi, a3); po = lo + hi;
                    float hn = cellup(pi, pf, pg, po, cst[gb]);
                    if (lane < HID) ((float*)s_h[2][pipe][pw][gb])[lane] = hn;
                }
            }
        }
        // per-pipeline named barrier: couples only this pipe's 3 warps
        asm volatile("bar.sync %0, 96;" :: "r"(bar_id) : "memory");
    }

    // ---- final FC on h2[T-1] by the L2 warps ----
    if (role == 2) {
        const int pfin = (T_LEN - 1) & 1;
#pragma unroll
        for (int gb = 0; gb < GB; gb++) {
            float hv = ((const float*)s_h[2][pipe][pfin][gb])[j];
            float p0 = (lane < HID) ? hv * fcw[j]       : 0.f;
            float p1 = (lane < HID) ? hv * fcw[HID + j] : 0.f;
#pragma unroll
            for (int off = 16; off > 0; off >>= 1) {
                p0 += __shfl_xor_sync(FULLM, p0, off);
                p1 += __shfl_xor_sync(FULLM, p1, off);
            }
            if (lane == 0) {
                out[(bbase + gb) * 2 + 0] = p0 + fcb[0];
                out[(bbase + gb) * 2 + 1] = p1 + fcb[1];
            }
        }
    }
}

extern "C" void kernel_launch(void* const* d_in, const int* in_sizes, int n_in,
                              void* d_out, int out_size) {
    const float* x    = (const float*)d_in[0];
    const float* wih0 = (const float*)d_in[1];
    const float* whh0 = (const float*)d_in[2];
    const float* bih0 = (const float*)d_in[3];
    const float* bhh0 = (const float*)d_in[4];
    const float* wih1 = (const float*)d_in[5];
    const float* whh1 = (const float*)d_in[6];
    const float* bih1 = (const float*)d_in[7];
    const float* bhh1 = (const float*)d_in[8];
    const float* wih2 = (const float*)d_in[9];
    const float* whh2 = (const float*)d_in[10];
    const float* bih2 = (const float*)d_in[11];
    const float* bhh2 = (const float*)d_in[12];
    const float* fcw  = (const float*)d_in[13];
    const float* fcb  = (const float*)d_in[14];
    float* out = (float*)d_out;

    // 1024 batches / (4 pipelines x 2 batches) = 128 blocks of 384 threads
    lstm3_pipe<<<128, NW * 32>>>(x, wih0, whh0, bih0, bhh0,
                                 wih1, whh1, bih1, bhh1,
                                 wih2, whh2, bih2, bhh2,
                                 fcw, fcb, out);
}

// round 10
// speedup vs baseline: 1.1471x; 1.1471x over previous
#include <cuda_runtime.h>
#include <cuda_bf16.h>

// 3-layer LSTM, B=1024, T=1024, H=20, IN=1, OUT=2, FC on last h2.
// R10: 2-warp teams per 2 batches. ALL weights register-resident across the
// team: A = {wih1, wih2, whh0[k0:9]}, B = {whh1, whh2, whh0[k10:19]}.
// B computes recurrent partials (h[t-1]) in parallel with A; A does the
// serial chain (cell updates, h publish). 2 team-local bar.sync per step.
// Zero weight SMEM traffic. 1024 warps, 8/SM on 128 SMs, A+B paired per SMSP.

#define T_LEN 1024
#define HID   20
#define FULLM 0xffffffffu

typedef unsigned long long u64;

__device__ __forceinline__ void ffma2(u64 &acc, u64 a, u64 b) {
    asm("fma.rn.f32x2 %0, %1, %2, %0;" : "+l"(acc) : "l"(a), "l"(b));
}
__device__ __forceinline__ float hadd(u64 v) {
    float lo, hi;
    asm("mov.b64 {%0, %1}, %2;" : "=f"(lo), "=f"(hi) : "l"(v));
    return lo + hi;
}

// ---- accurate fast activations (MUFU EX2/RCP, ~1e-6 err) ----
__device__ __forceinline__ float fsig(float x) {
    float e = __expf(-x);
    return __fdividef(1.0f, 1.0f + e);
}
__device__ __forceinline__ float ftanh(float x) {
    float ax = fabsf(x);
    float e  = __expf(-2.0f * ax);
    float r  = __fdividef(1.0f - e, 1.0f + e);
    return copysignf(r, x);
}
__device__ __forceinline__ float cellup(float pi, float pf, float pg, float po,
                                        float &c) {
    c = fsig(pf) * c + fsig(pi) * ftanh(pg);
    return fsig(po) * ftanh(c);
}

// 20 k-steps: accs a_g = {sum even-k, sum odd-k}; weights W[g*10+m] = {w[2m],w[2m+1]}
__device__ __forceinline__ void mac20(u64 &a0, u64 &a1, u64 &a2, u64 &a3,
                                      const float* __restrict__ h,
                                      const u64* __restrict__ W)
{
    const ulonglong2* q = (const ulonglong2*)h;
#pragma unroll
    for (int i = 0; i < 5; i++) {
        ulonglong2 v = q[i];                  // {h4i,h4i+1},{h4i+2,h4i+3}
        ffma2(a0, v.x, W[2*i]);      ffma2(a1, v.x, W[10 + 2*i]);
        ffma2(a2, v.x, W[20 + 2*i]); ffma2(a3, v.x, W[30 + 2*i]);
        ffma2(a0, v.y, W[2*i+1]);      ffma2(a1, v.y, W[10 + 2*i+1]);
        ffma2(a2, v.y, W[20 + 2*i+1]); ffma2(a3, v.y, W[30 + 2*i+1]);
    }
}
// k = 0..9 (kpairs 0..4); W[g*5+m]
__device__ __forceinline__ void mac10_lo(u64 &a0, u64 &a1, u64 &a2, u64 &a3,
                                         const float* __restrict__ h,
                                         const u64* __restrict__ W)
{
    const ulonglong2* q = (const ulonglong2*)h;
    ulonglong2 v0 = q[0], v1 = q[1];
    u64 v2 = ((const u64*)h)[4];
    ffma2(a0, v0.x, W[0]);  ffma2(a1, v0.x, W[5]);  ffma2(a2, v0.x, W[10]); ffma2(a3, v0.x, W[15]);
    ffma2(a0, v0.y, W[1]);  ffma2(a1, v0.y, W[6]);  ffma2(a2, v0.y, W[11]); ffma2(a3, v0.y, W[16]);
    ffma2(a0, v1.x, W[2]);  ffma2(a1, v1.x, W[7]);  ffma2(a2, v1.x, W[12]); ffma2(a3, v1.x, W[17]);
    ffma2(a0, v1.y, W[3]);  ffma2(a1, v1.y, W[8]);  ffma2(a2, v1.y, W[13]); ffma2(a3, v1.y, W[18]);
    ffma2(a0, v2,   W[4]);  ffma2(a1, v2,   W[9]);  ffma2(a2, v2,   W[14]); ffma2(a3, v2,   W[19]);
}
// k = 10..19 (kpairs 5..9); W[g*5+m]
__device__ __forceinline__ void mac10_hi(u64 &a0, u64 &a1, u64 &a2, u64 &a3,
                                         const float* __restrict__ h,
                                         const u64* __restrict__ W)
{
    const u64* p = (const u64*)h;
    u64 v0 = p[5];
    ulonglong2 v1 = *(const ulonglong2*)(p + 6);
    ulonglong2 v2 = *(const ulonglong2*)(p + 8);
    ffma2(a0, v0,   W[0]);  ffma2(a1, v0,   W[5]);  ffma2(a2, v0,   W[10]); ffma2(a3, v0,   W[15]);
    ffma2(a0, v1.x, W[1]);  ffma2(a1, v1.x, W[6]);  ffma2(a2, v1.x, W[11]); ffma2(a3, v1.x, W[16]);
    ffma2(a0, v1.y, W[2]);  ffma2(a1, v1.y, W[7]);  ffma2(a2, v1.y, W[12]); ffma2(a3, v1.y, W[17]);
    ffma2(a0, v2.x, W[3]);  ffma2(a1, v2.x, W[8]);  ffma2(a2, v2.x, W[13]); ffma2(a3, v2.x, W[18]);
    ffma2(a0, v2.y, W[4]);  ffma2(a1, v2.y, W[9]);  ffma2(a2, v2.y, W[14]); ffma2(a3, v2.y, W[19]);
}

struct TeamSmem {
    float4 h[3][2][5];        // [layer][batch][20 floats]
    float4 P[3][2][HID];      // partials per unit: {pi,pf,pg,po}
};

__global__ void __launch_bounds__(256, 1)
lstm3_team(const float* __restrict__ x,
           const float* __restrict__ wih0, const float* __restrict__ whh0,
           const float* __restrict__ bih0, const float* __restrict__ bhh0,
           const float* __restrict__ wih1, const float* __restrict__ whh1,
           const float* __restrict__ bih1, const float* __restrict__ bhh1,
           const float* __restrict__ wih2, const float* __restrict__ whh2,
           const float* __restrict__ bih2, const float* __restrict__ bhh2,
           const float* __restrict__ fcw,  const float* __restrict__ fcb,
           float* __restrict__ out)
{
    __shared__ TeamSmem ts[4];

    const int tid  = threadIdx.x;
    const int lane = tid & 31;
    const int wid  = tid >> 5;

    // zero h buffers
    {
        float4* p = &ts[0].h[0][0][0];
        for (int i = tid; i < 4 * 3 * 2 * 5; i += 256) {
            // stride over the h arrays of all teams (struct-safe: per team)
        }
    }
    for (int t = 0; t < 4; t++) {
        float4* p = &ts[t].h[0][0][0];
        for (int i = tid; i < 3 * 2 * 5; i += 256)
            p[i] = make_float4(0.f, 0.f, 0.f, 0.f);
    }
    __syncthreads();

    const int  team  = wid & 3;        // SMSP k hosts wid k (A) + wid k+4 (B)
    const bool isA   = (wid < 4);
    const int  barid = 1 + team;
    const int  j     = (lane < HID) ? lane : (HID - 1);
    const int  b0    = blockIdx.x * 8 + team * 2;

    const float* h0p[2] = { (const float*)&ts[team].h[0][0][0], (const float*)&ts[team].h[0][1][0] };
    const float* h1p[2] = { (const float*)&ts[team].h[1][0][0], (const float*)&ts[team].h[1][1][0] };
    const float* h2p[2] = { (const float*)&ts[team].h[2][0][0], (const float*)&ts[team].h[2][1][0] };

    if (isA) {
        // ---- A: wih1, wih2 (kpair fmt) + whh0 k0:9 + wih0 column ----
        u64 W1[40], W2[40], W0A[20];
        float wx[4];
#pragma unroll
        for (int g = 0; g < 4; g++) {
            const int row = g * HID + j;
#pragma unroll
            for (int m = 0; m < 10; m++) {
                W1[g * 10 + m] = *(const u64*)(wih1 + row * HID + 2 * m);
                W2[g * 10 + m] = *(const u64*)(wih2 + row * HID + 2 * m);
            }
#pragma unroll
            for (int m = 0; m < 5; m++)
                W0A[g * 5 + m] = *(const u64*)(whh0 + row * HID + 2 * m);
            wx[g] = wih0[row];
        }

        float c00 = 0.f, c01 = 0.f, c10 = 0.f, c11 = 0.f, c20 = 0.f, c21 = 0.f;
        float h2n0 = 0.f, h2n1 = 0.f;
        float xs0 = 0.f, xs1 = 0.f;

        for (int n = 0; n < T_LEN; n++) {
            if ((n & 31) == 0) {
                xs0 = x[(b0    ) * T_LEN + n + lane];
                xs1 = x[(b0 + 1) * T_LEN + n + lane];
            }
            float xv0 = __shfl_sync(FULLM, xs0, n & 31);
            float xv1 = __shfl_sync(FULLM, xs1, n & 31);

            // phase 1: whh0 low-half partials vs h0[t-1] (both batches)
            u64 p00 = 0, p01 = 0, p02 = 0, p03 = 0;
            u64 p10 = 0, p11 = 0, p12 = 0, p13 = 0;
            mac10_lo(p00, p01, p02, p03, h0p[0], W0A);
            mac10_lo(p10, p11, p12, p13, h0p[1], W0A);

            asm volatile("bar.sync %0, 64;" :: "r"(barid) : "memory");

            // phase 2, L0: combine with B's high-half + x term; cell update
            {
                float4 Q0 = ts[team].P[0][0][j];
                float4 Q1 = ts[team].P[0][1][j];
                float g0i = fmaf(xv0, wx[0], hadd(p00) + Q0.x);
                float g0f = fmaf(xv0, wx[1], hadd(p01) + Q0.y);
                float g0g = fmaf(xv0, wx[2], hadd(p02) + Q0.z);
                float g0o = fmaf(xv0, wx[3], hadd(p03) + Q0.w);
                float g1i = fmaf(xv1, wx[0], hadd(p10) + Q1.x);
                float g1f = fmaf(xv1, wx[1], hadd(p11) + Q1.y);
                float g1g = fmaf(xv1, wx[2], hadd(p12) + Q1.z);
                float g1o = fmaf(xv1, wx[3], hadd(p13) + Q1.w);
                float h0n0 = cellup(g0i, g0f, g0g, g0o, c00);
                float h0n1 = cellup(g1i, g1f, g1g, g1o, c01);
                if (lane < HID) {
                    ((float*)&ts[team].h[0][0][0])[lane] = h0n0;
                    ((float*)&ts[team].h[0][1][0])[lane] = h0n1;
                }
            }
            __syncwarp();

            // L1: wih1 * h0[t] + B's whh1 partial
            {
                u64 a0 = 0, a1 = 0, a2 = 0, a3 = 0;
                u64 d0 = 0, d1 = 0, d2 = 0, d3 = 0;
                mac20(a0, a1, a2, a3, h0p[0], W1);
                mac20(d0, d1, d2, d3, h0p[1], W1);
                float4 Q0 = ts[team].P[1][0][j];
                float4 Q1 = ts[team].P[1][1][j];
                float h1n0 = cellup(hadd(a0) + Q0.x, hadd(a1) + Q0.y,
                                    hadd(a2) + Q0.z, hadd(a3) + Q0.w, c10);
                float h1n1 = cellup(hadd(d0) + Q1.x, hadd(d1) + Q1.y,
                                    hadd(d2) + Q1.z, hadd(d3) + Q1.w, c11);
                if (lane < HID) {
                    ((float*)&ts[team].h[1][0][0])[lane] = h1n0;
                    ((float*)&ts[team].h[1][1][0])[lane] = h1n1;
                }
            }
            __syncwarp();

            // L2: wih2 * h1[t] + B's whh2 partial
            {
                u64 a0 = 0, a1 = 0, a2 = 0, a3 = 0;
                u64 d0 = 0, d1 = 0, d2 = 0, d3 = 0;
                mac20(a0, a1, a2, a3, h1p[0], W2);
                mac20(d0, d1, d2, d3, h1p[1], W2);
                float4 Q0 = ts[team].P[2][0][j];
                float4 Q1 = ts[team].P[2][1][j];
                h2n0 = cellup(hadd(a0) + Q0.x, hadd(a1) + Q0.y,
                              hadd(a2) + Q0.z, hadd(a3) + Q0.w, c20);
                h2n1 = cellup(hadd(d0) + Q1.x, hadd(d1) + Q1.y,
                              hadd(d2) + Q1.z, hadd(d3) + Q1.w, c21);
                if (lane < HID) {
                    ((float*)&ts[team].h[2][0][0])[lane] = h2n0;
                    ((float*)&ts[team].h[2][1][0])[lane] = h2n1;
                }
            }

            asm volatile("bar.sync %0, 64;" :: "r"(barid) : "memory");
        }

        // ---- final FC: out[b] = fc_w @ h2 + fc_b ----
        float w0 = fcw[j], w1 = fcw[HID + j];
        float p0a = (lane < HID) ? h2n0 * w0 : 0.f;
        float p1a = (lane < HID) ? h2n0 * w1 : 0.f;
        float p0b = (lane < HID) ? h2n1 * w0 : 0.f;
        float p1b = (lane < HID) ? h2n1 * w1 : 0.f;
#pragma unroll
        for (int off = 16; off > 0; off >>= 1) {
            p0a += __shfl_xor_sync(FULLM, p0a, off);
            p1a += __shfl_xor_sync(FULLM, p1a, off);
            p0b += __shfl_xor_sync(FULLM, p0b, off);
            p1b += __shfl_xor_sync(FULLM, p1b, off);
        }
        if (lane == 0) {
            out[(b0    ) * 2 + 0] = p0a + fcb[0];
            out[(b0    ) * 2 + 1] = p1a + fcb[1];
            out[(b0 + 1) * 2 + 0] = p0b + fcb[0];
            out[(b0 + 1) * 2 + 1] = p1b + fcb[1];
        }
    } else {
        // ---- B: whh1, whh2 (kpair fmt) + whh0 k10:19 + biases ----
        u64 WB1[40], WB2[40], W0B[20];
        float bs[3][4];
#pragma unroll
        for (int g = 0; g < 4; g++) {
            const int row = g * HID + j;
#pragma unroll
            for (int m = 0; m < 10; m++) {
                WB1[g * 10 + m] = *(const u64*)(whh1 + row * HID + 2 * m);
                WB2[g * 10 + m] = *(const u64*)(whh2 + row * HID + 2 * m);
            }
#pragma unroll
            for (int m = 0; m < 5; m++)
                W0B[g * 5 + m] = *(const u64*)(whh0 + row * HID + 2 * (5 + m));
            bs[0][g] = bih0[row] + bhh0[row];
            bs[1][g] = bih1[row] + bhh1[row];
            bs[2][g] = bih2[row] + bhh2[row];
        }

        for (int n = 0; n < T_LEN; n++) {
            // recurrent partials vs state[t-1], published with biases folded in
#pragma unroll
            for (int b = 0; b < 2; b++) {
                u64 a0 = 0, a1 = 0, a2 = 0, a3 = 0;
                mac10_hi(a0, a1, a2, a3, h0p[b], W0B);
                if (lane < HID)
                    ts[team].P[0][b][j] = make_float4(hadd(a0) + bs[0][0],
                                                      hadd(a1) + bs[0][1],
                                                      hadd(a2) + bs[0][2],
                                                      hadd(a3) + bs[0][3]);
                u64 e0 = 0, e1 = 0, e2 = 0, e3 = 0;
                mac20(e0, e1, e2, e3, h1p[b], WB1);
                if (lane < HID)
                    ts[team].P[1][b][j] = make_float4(hadd(e0) + bs[1][0],
                                                      hadd(e1) + bs[1][1],
                                                      hadd(e2) + bs[1][2],
                                                      hadd(e3) + bs[1][3]);
                u64 f0 = 0, f1 = 0, f2 = 0, f3 = 0;
                mac20(f0, f1, f2, f3, h2p[b], WB2);
                if (lane < HID)
                    ts[team].P[2][b][j] = make_float4(hadd(f0) + bs[2][0],
                                                      hadd(f1) + bs[2][1],
                                                      hadd(f2) + bs[2][2],
                                                      hadd(f3) + bs[2][3]);
            }
            asm volatile("bar.sync %0, 64;" :: "r"(barid) : "memory");
            // A runs the serial chain; B just meets it at the end-of-step bar
            asm volatile("bar.sync %0, 64;" :: "r"(barid) : "memory");
        }
    }
}

extern "C" void kernel_launch(void* const* d_in, const int* in_sizes, int n_in,
                              void* d_out, int out_size) {
    const float* x    = (const float*)d_in[0];
    const float* wih0 = (const float*)d_in[1];
    const float* whh0 = (const float*)d_in[2];
    const float* bih0 = (const float*)d_in[3];
    const float* bhh0 = (const float*)d_in[4];
    const float* wih1 = (const float*)d_in[5];
    const float* whh1 = (const float*)d_in[6];
    const float* bih1 = (const float*)d_in[7];
    const float* bhh1 = (const float*)d_in[8];
    const float* wih2 = (const float*)d_in[9];
    const float* whh2 = (const float*)d_in[10];
    const float* bih2 = (const float*)d_in[11];
    const float* bhh2 = (const float*)d_in[12];
    const float* fcw  = (const float*)d_in[13];
    const float* fcb  = (const float*)d_in[14];
    float* out = (float*)d_out;

    // 1024 batches / (4 teams x 2 batches) = 128 blocks of 256 threads
    lstm3_team<<<128, 256>>>(x, wih0, whh0, bih0, bhh0,
                             wih1, whh1, bih1, bhh1,
                             wih2, whh2, bih2, bhh2,
                             fcw, fcb, out);
}

// round 11
// speedup vs baseline: 1.2754x; 1.1119x over previous
#include <cuda_runtime.h>
#include <cuda_bf16.h>

// 3-layer LSTM, B=1024, T=1024, H=20, IN=1, OUT=2, FC on last h2.
// R11: R8 layer-pipeline skeleton + gate-row split over all 32 lanes.
// Lane l owns gate rows {l, l+32, 64+(l&15)} with weights in registers;
// h broadcast from SMEM; row sums exchanged via per-warp scratch (unit-major
// float4), cell update by lanes 0..19. 147 blocks x 7 batches (pipes 4+3).

#define T_LEN 1024
#define HID   20
#define FULLM 0xffffffffu
#define NW    6

typedef unsigned long long u64;

__device__ __forceinline__ void ffma2(u64 &acc, u64 a, u64 b) {
    asm("fma.rn.f32x2 %0, %1, %2, %0;" : "+l"(acc) : "l"(a), "l"(b));
}
__device__ __forceinline__ float hadd(u64 v) {
    float lo, hi;
    asm("mov.b64 {%0, %1}, %2;" : "=f"(lo), "=f"(hi) : "l"(v));
    return lo + hi;
}

// ---- accurate fast activations (MUFU EX2/RCP, ~1e-6 err) ----
__device__ __forceinline__ float fsig(float x) {
    float e = __expf(-x);
    return __fdividef(1.0f, 1.0f + e);
}
__device__ __forceinline__ float ftanh(float x) {
    float ax = fabsf(x);
    float e  = __expf(-2.0f * ax);
    float r  = __fdividef(1.0f - e, 1.0f + e);
    return copysignf(r, x);
}
__device__ __forceinline__ float cellup(float pi, float pf, float pg, float po,
                                        float &c) {
    c = fsig(pf) * c + fsig(pi) * ftanh(pg);
    return fsig(po) * ftanh(c);
}

__global__ void __launch_bounds__(NW * 32, 1)
lstm3_rows(const float* __restrict__ x,
           const float* __restrict__ wih0, const float* __restrict__ whh0,
           const float* __restrict__ bih0, const float* __restrict__ bhh0,
           const float* __restrict__ wih1, const float* __restrict__ whh1,
           const float* __restrict__ bih1, const float* __restrict__ bhh1,
           const float* __restrict__ wih2, const float* __restrict__ whh2,
           const float* __restrict__ bih2, const float* __restrict__ bhh2,
           const float* __restrict__ fcw,  const float* __restrict__ fcb,
           float* __restrict__ out)
{
    // h buffers: [layer][pipe][parity][gb][20 floats]
    __shared__ __align__(16) float4 s_h[3][2][2][4][5];
    // per-warp row-sum scratch, unit-major: ps[u*4+g]
    __shared__ __align__(16) float s_ps[NW][80];

    const int tid  = threadIdx.x;
    const int lane = tid & 31;
    const int wid  = tid >> 5;

    {   // zero h buffers
        float4* p = &s_h[0][0][0][0][0];
        for (int i = tid; i < 3 * 2 * 2 * 4 * 5; i += NW * 32)
            p[i] = make_float4(0.f, 0.f, 0.f, 0.f);
    }
    __syncthreads();

    // role map: S0={L1p0,L0p0} S1={L2p0,L0p1} S2={L1p1} S3={L2p1}
    int role, pipe;
    if (wid < 4) { role = 1 + (wid & 1); pipe = wid >> 1; }
    else         { role = 0;             pipe = wid - 4;  }

    const int GBn   = (pipe == 0) ? 4 : 3;          // 7 batches per block
    const int bbase = blockIdx.x * 7 + pipe * 4;

    // gate-row assignment for this lane
    const int rA = lane;
    const int rB = lane + 32;
    const int rC = 64 + (lane & 15);                // lanes 16..31 shadow
    const int jc = (lane < HID) ? lane : (HID - 1);

    const int adA = (rA % 20) * 4 + rA / 20;
    const int adB = (rB % 20) * 4 + rB / 20;
    const int adC = (rC % 20) * 4 + rC / 20;
    float* __restrict__ ps = s_ps[wid];

    // ---- per-lane register weights ----
    // L0 (K=20):  WA/WB/WC[0..9]   = whh0 row k-pairs
    // L1/L2 (K=40): [0..9] = wih row, [10..19] = whh row
    u64 WA[20], WB[20], WC[20];
    float4 Bini, wx4 = make_float4(0.f, 0.f, 0.f, 0.f);
    {
        const float* wi = (role == 0) ? wih0 : ((role == 1) ? wih1 : wih2);
        const float* wh = (role == 0) ? whh0 : ((role == 1) ? whh1 : whh2);
        const float* bi = (role == 0) ? bih0 : ((role == 1) ? bih1 : bih2);
        const float* bh = (role == 0) ? bhh0 : ((role == 1) ? bhh1 : bhh2);
        if (role == 0) {
#pragma unroll
            for (int m = 0; m < 10; m++) {
                WA[m] = *(const u64*)(wh + rA * HID + 2 * m);
                WB[m] = *(const u64*)(wh + rB * HID + 2 * m);
                WC[m] = *(const u64*)(wh + rC * HID + 2 * m);
            }
            wx4 = make_float4(wi[jc], wi[20 + jc], wi[40 + jc], wi[60 + jc]);
        } else {
#pragma unroll
            for (int m = 0; m < 10; m++) {
                WA[m]      = *(const u64*)(wi + rA * HID + 2 * m);
                WA[10 + m] = *(const u64*)(wh + rA * HID + 2 * m);
                WB[m]      = *(const u64*)(wi + rB * HID + 2 * m);
                WB[10 + m] = *(const u64*)(wh + rB * HID + 2 * m);
                WC[m]      = *(const u64*)(wi + rC * HID + 2 * m);
                WC[10 + m] = *(const u64*)(wh + rC * HID + 2 * m);
            }
        }
        Bini = make_float4(bi[jc]      + bh[jc],      bi[20 + jc] + bh[20 + jc],
                           bi[40 + jc] + bh[40 + jc], bi[60 + jc] + bh[60 + jc]);
    }

    float cst[4] = {0.f, 0.f, 0.f, 0.f};
    float xs[4];

    // pipeline: step n -> L0 computes t=n, L1 t=n-1, L2 t=n-2
    for (int n = 0; n <= T_LEN + 1; n++) {
        if (role == 0) {
            if (n < T_LEN) {
                if ((n & 31) == 0) {
#pragma unroll
                    for (int gb = 0; gb < 4; gb++) {
                        if (gb >= GBn) break;
                        int bc = bbase + gb; if (bc > 1023) bc = 1023;
                        xs[gb] = x[(long)bc * T_LEN + n + lane];
                    }
                }
                const int pw = n & 1, pr = pw ^ 1;
#pragma unroll
                for (int gb = 0; gb < 4; gb++) {
                    if (gb >= GBn) break;
                    float xv = __shfl_sync(FULLM, xs[gb], n & 31);
                    const ulonglong2* hp =
                        (const ulonglong2*)&s_h[0][pipe][pr][gb][0];
                    u64 aA = 0, aB = 0, aC = 0;
#pragma unroll
                    for (int i = 0; i < 5; i++) {
                        ulonglong2 v = hp[i];
                        ffma2(aA, v.x, WA[2*i]); ffma2(aA, v.y, WA[2*i+1]);
                        ffma2(aB, v.x, WB[2*i]); ffma2(aB, v.y, WB[2*i+1]);
                        ffma2(aC, v.x, WC[2*i]); ffma2(aC, v.y, WC[2*i+1]);
                    }
                    ps[adA] = hadd(aA);
                    ps[adB] = hadd(aB);
                    if (lane < 16) ps[adC] = hadd(aC);
                    __syncwarp();
                    float4 G = *(const float4*)&ps[jc * 4];
                    float gi = fmaf(xv, wx4.x, G.x + Bini.x);
                    float gf = fmaf(xv, wx4.y, G.y + Bini.y);
                    float gg = fmaf(xv, wx4.z, G.z + Bini.z);
                    float go = fmaf(xv, wx4.w, G.w + Bini.w);
                    float hn = cellup(gi, gf, gg, go, cst[gb]);
                    if (lane < HID)
                        ((float*)&s_h[0][pipe][pw][gb][0])[lane] = hn;
                    __syncwarp();
                }
            }
        } else if (role == 1) {
            if (n >= 1 && n <= T_LEN) {
                const int t = n - 1, pw = t & 1, pr = pw ^ 1;
#pragma unroll
                for (int gb = 0; gb < 4; gb++) {
                    if (gb >= GBn) break;
                    const ulonglong2* h0 =
                        (const ulonglong2*)&s_h[0][pipe][pw][gb][0];  // h0[t]
                    const ulonglong2* h1 =
                        (const ulonglong2*)&s_h[1][pipe][pr][gb][0];  // h1[t-1]
                    u64 aA = 0, aB = 0, aC = 0;
#pragma unroll
                    for (int i = 0; i < 5; i++) {
                        ulonglong2 v = h0[i];
                        ffma2(aA, v.x, WA[2*i]); ffma2(aA, v.y, WA[2*i+1]);
                        ffma2(aB, v.x, WB[2*i]); ffma2(aB, v.y, WB[2*i+1]);
                        ffma2(aC, v.x, WC[2*i]); ffma2(aC, v.y, WC[2*i+1]);
                    }
#pragma unroll
                    for (int i = 0; i < 5; i++) {
                        ulonglong2 v = h1[i];
                        ffma2(aA, v.x, WA[10+2*i]); ffma2(aA, v.y, WA[10+2*i+1]);
                        ffma2(aB, v.x, WB[10+2*i]); ffma2(aB, v.y, WB[10+2*i+1]);
                        ffma2(aC, v.x, WC[10+2*i]); ffma2(aC, v.y, WC[10+2*i+1]);
                    }
                    ps[adA] = hadd(aA);
                    ps[adB] = hadd(aB);
                    if (lane < 16) ps[adC] = hadd(aC);
                    __syncwarp();
                    float4 G = *(const float4*)&ps[jc * 4];
                    float hn = cellup(G.x + Bini.x, G.y + Bini.y,
                                      G.z + Bini.z, G.w + Bini.w, cst[gb]);
                    if (lane < HID)
                        ((float*)&s_h[1][pipe][pw][gb][0])[lane] = hn;
                    __syncwarp();
                }
            }
        } else {
            if (n >= 2) {
                const int t = n - 2, pw = t & 1, pr = pw ^ 1;
#pragma unroll
                for (int gb = 0; gb < 4; gb++) {
                    if (gb >= GBn) break;
                    const ulonglong2* h1 =
                        (const ulonglong2*)&s_h[1][pipe][pw][gb][0];  // h1[t]
                    const ulonglong2* h2 =
                        (const ulonglong2*)&s_h[2][pipe][pr][gb][0];  // h2[t-1]
                    u64 aA = 0, aB = 0, aC = 0;
#pragma unroll
                    for (int i = 0; i < 5; i++) {
                        ulonglong2 v = h1[i];
                        ffma2(aA, v.x, WA[2*i]); ffma2(aA, v.y, WA[2*i+1]);
                        ffma2(aB, v.x, WB[2*i]); ffma2(aB, v.y, WB[2*i+1]);
                        ffma2(aC, v.x, WC[2*i]); ffma2(aC, v.y, WC[2*i+1]);
                    }
#pragma unroll
                    for (int i = 0; i < 5; i++) {
                        ulonglong2 v = h2[i];
                        ffma2(aA, v.x, WA[10+2*i]); ffma2(aA, v.y, WA[10+2*i+1]);
                        ffma2(aB, v.x, WB[10+2*i]); ffma2(aB, v.y, WB[10+2*i+1]);
                        ffma2(aC, v.x, WC[10+2*i]); ffma2(aC, v.y, WC[10+2*i+1]);
                    }
                    ps[adA] = hadd(aA);
                    ps[adB] = hadd(aB);
                    if (lane < 16) ps[adC] = hadd(aC);
                    __syncwarp();
                    float4 G = *(const float4*)&ps[jc * 4];
                    float hn = cellup(G.x + Bini.x, G.y + Bini.y,
                                      G.z + Bini.z, G.w + Bini.w, cst[gb]);
                    if (lane < HID)
                        ((float*)&s_h[2][pipe][pw][gb][0])[lane] = hn;
                    __syncwarp();
                }
            }
        }
        __syncthreads();
    }

    // ---- final FC on h2[T-1] by the L2 warps ----
    if (role == 2) {
        const int pfin = (T_LEN - 1) & 1;
#pragma unroll
        for (int gb = 0; gb < 4; gb++) {
            if (gb >= GBn) break;
            const int b = bbase + gb;
            float hv = ((const float*)&s_h[2][pipe][pfin][gb][0])[jc];
            float p0 = (lane < HID) ? hv * fcw[jc]       : 0.f;
            float p1 = (lane < HID) ? hv * fcw[HID + jc] : 0.f;
#pragma unroll
            for (int off = 16; off > 0; off >>= 1) {
                p0 += __shfl_xor_sync(FULLM, p0, off);
                p1 += __shfl_xor_sync(FULLM, p1, off);
            }
            if (lane == 0 && b < 1024) {
                out[b * 2 + 0] = p0 + fcb[0];
                out[b * 2 + 1] = p1 + fcb[1];
            }
        }
    }
}

extern "C" void kernel_launch(void* const* d_in, const int* in_sizes, int n_in,
                              void* d_out, int out_size) {
    const float* x    = (const float*)d_in[0];
    const float* wih0 = (const float*)d_in[1];
    const float* whh0 = (const float*)d_in[2];
    const float* bih0 = (const float*)d_in[3];
    const float* bhh0 = (const float*)d_in[4];
    const float* wih1 = (const float*)d_in[5];
    const float* whh1 = (const float*)d_in[6];
    const float* bih1 = (const float*)d_in[7];
    const float* bhh1 = (const float*)d_in[8];
    const float* wih2 = (const float*)d_in[9];
    const float* whh2 = (const float*)d_in[10];
    const float* bih2 = (const float*)d_in[11];
    const float* bhh2 = (const float*)d_in[12];
    const float* fcw  = (const float*)d_in[13];
    const float* fcb  = (const float*)d_in[14];
    float* out = (float*)d_out;

    // 147 blocks x 7 batches (pipes of 4 and 3): 1029 slots for 1024 batches
    lstm3_rows<<<147, NW * 32>>>(x, wih0, whh0, bih0, bhh0,
                                 wih1, whh1, bih1, bhh1,
                                 wih2, whh2, bih2, bhh2,
                                 fcw, fcb, out);
}